// round 10
// baseline (speedup 1.0000x reference)
#include <cuda_runtime.h>

// diff[k] = (f[k-3] - f[k+2]) / 5 with zero-padding outside [0,n)
// change[k] = diff[k]^2 for k>=1, change[0] = 0
// out[k] = (1 - change[k]/S)^5 * f[k],  S = sum(change)
//
// Single persistent kernel. Each block owns a CONTIGUOUS region of 1024-elem
// units (near-equal split -> <=1-unit imbalance). Units processed in batched
// groups (MLP-deep loads + shuffle halo). Phase2 re-walks the region in
// REVERSE order so phase1's most recent lines are L1-hot. Grid sync via
// monotonic generation counters (graph-replay safe).

#define TPB 256
#define UNIT (TPB * 4)                 // 1024 elems per unit
#define GRID 888                       // 148 SMs x 6 blocks, fully resident
#define FULL 0xffffffffu

__device__ float g_part[GRID];
__device__ float g_invS;
__device__ unsigned long long g_arrive  = 0;
__device__ unsigned long long g_release = 0;

// ---------------- phase-1 group: K units starting at element 'base' --------
template<int K>
__device__ __forceinline__ float p1_group(const float* __restrict__ f,
                                          int base, int tid, int lane, int n) {
    float acc = 0.0f;
    if (base > 0 && base + K * UNIT + 5 <= n) {
        float4 c[K];
        #pragma unroll
        for (int j = 0; j < K; j++)
            c[j] = __ldg(reinterpret_cast<const float4*>(f + base + j * UNIT + tid * 4));
        #pragma unroll
        for (int j = 0; j < K; j++) {
            const int v = base + j * UNIT + tid * 4;
            float m3 = __shfl_up_sync(FULL, c[j].y, 1);
            float m2 = __shfl_up_sync(FULL, c[j].z, 1);
            float m1 = __shfl_up_sync(FULL, c[j].w, 1);
            float p4 = __shfl_down_sync(FULL, c[j].x, 1);
            float p5 = __shfl_down_sync(FULL, c[j].y, 1);
            if (lane == 0) {
                m3 = __ldg(f + v - 3);
                m2 = __ldg(f + v - 2);
                m1 = __ldg(f + v - 1);
            }
            if (lane == 31) {
                p4 = __ldg(f + v + 4);
                p5 = __ldg(f + v + 5);
            }
            float d0 = (m3     - c[j].z) * 0.2f;
            float d1 = (m2     - c[j].w) * 0.2f;
            float d2 = (m1     - p4    ) * 0.2f;
            float d3 = (c[j].x - p5    ) * 0.2f;
            acc += d0 * d0 + d1 * d1 + d2 * d2 + d3 * d3;
        }
    } else {
        #pragma unroll
        for (int j = 0; j < K; j++) {
            const int v = base + j * UNIT + tid * 4;
            if (v + 3 < n) {
                float4 c = __ldg(reinterpret_cast<const float4*>(f + v));
                float m3 = (v >= 3)     ? __ldg(f + v - 3) : 0.0f;
                float m2 = (v >= 2)     ? __ldg(f + v - 2) : 0.0f;
                float m1 = (v >= 1)     ? __ldg(f + v - 1) : 0.0f;
                float p4 = (v + 4 < n)  ? __ldg(f + v + 4) : 0.0f;
                float p5 = (v + 5 < n)  ? __ldg(f + v + 5) : 0.0f;
                float d0 = (m3  - c.z) * 0.2f;
                float d1 = (m2  - c.w) * 0.2f;
                float d2 = (m1  - p4 ) * 0.2f;
                float d3 = (c.x - p5 ) * 0.2f;
                float c0 = (v == 0) ? 0.0f : d0 * d0;
                acc += c0 + d1 * d1 + d2 * d2 + d3 * d3;
            } else if (v < n) {
                for (int k = v; k < n; k++) {
                    float l = (k >= 3)    ? __ldg(f + k - 3) : 0.0f;
                    float r = (k + 2 < n) ? __ldg(f + k + 2) : 0.0f;
                    float d = (l - r) * 0.2f;
                    if (k != 0) acc += d * d;
                }
            }
        }
    }
    return acc;
}

// ---------------- phase-2 group ---------------------------------------------
template<int K>
__device__ __forceinline__ void p2_group(const float* __restrict__ f,
                                         float* __restrict__ out,
                                         int base, int tid, int lane, int n,
                                         float invS) {
    if (base > 0 && base + K * UNIT + 5 <= n) {
        float4 c[K];
        #pragma unroll
        for (int j = 0; j < K; j++)
            c[j] = __ldg(reinterpret_cast<const float4*>(f + base + j * UNIT + tid * 4));
        #pragma unroll
        for (int j = 0; j < K; j++) {
            const int v = base + j * UNIT + tid * 4;
            float m3 = __shfl_up_sync(FULL, c[j].y, 1);
            float m2 = __shfl_up_sync(FULL, c[j].z, 1);
            float m1 = __shfl_up_sync(FULL, c[j].w, 1);
            float p4 = __shfl_down_sync(FULL, c[j].x, 1);
            float p5 = __shfl_down_sync(FULL, c[j].y, 1);
            if (lane == 0) {
                m3 = __ldg(f + v - 3);
                m2 = __ldg(f + v - 2);
                m1 = __ldg(f + v - 1);
            }
            if (lane == 31) {
                p4 = __ldg(f + v + 4);
                p5 = __ldg(f + v + 5);
            }
            float d0 = (m3     - c[j].z) * 0.2f;
            float d1 = (m2     - c[j].w) * 0.2f;
            float d2 = (m1     - p4    ) * 0.2f;
            float d3 = (c[j].x - p5    ) * 0.2f;
            float t0 = 1.0f - d0 * d0 * invS;
            float t1 = 1.0f - d1 * d1 * invS;
            float t2 = 1.0f - d2 * d2 * invS;
            float t3 = 1.0f - d3 * d3 * invS;
            float q0 = t0 * t0, q1 = t1 * t1, q2 = t2 * t2, q3 = t3 * t3;
            float4 o;
            o.x = q0 * q0 * t0 * c[j].x;
            o.y = q1 * q1 * t1 * c[j].y;
            o.z = q2 * q2 * t2 * c[j].z;
            o.w = q3 * q3 * t3 * c[j].w;
            __stcs(reinterpret_cast<float4*>(out + v), o);
        }
    } else {
        #pragma unroll
        for (int j = 0; j < K; j++) {
            const int v = base + j * UNIT + tid * 4;
            if (v + 3 < n) {
                float4 c = __ldg(reinterpret_cast<const float4*>(f + v));
                float m3 = (v >= 3)    ? __ldg(f + v - 3) : 0.0f;
                float m2 = (v >= 2)    ? __ldg(f + v - 2) : 0.0f;
                float m1 = (v >= 1)    ? __ldg(f + v - 1) : 0.0f;
                float p4 = (v + 4 < n) ? __ldg(f + v + 4) : 0.0f;
                float p5 = (v + 5 < n) ? __ldg(f + v + 5) : 0.0f;
                float d0 = (m3  - c.z) * 0.2f;
                float d1 = (m2  - c.w) * 0.2f;
                float d2 = (m1  - p4 ) * 0.2f;
                float d3 = (c.x - p5 ) * 0.2f;
                float c0 = (v == 0) ? 0.0f : d0 * d0 * invS;
                float t0 = 1.0f - c0;
                float t1 = 1.0f - d1 * d1 * invS;
                float t2 = 1.0f - d2 * d2 * invS;
                float t3 = 1.0f - d3 * d3 * invS;
                float q0 = t0 * t0, q1 = t1 * t1, q2 = t2 * t2, q3 = t3 * t3;
                float4 o;
                o.x = q0 * q0 * t0 * c.x;
                o.y = q1 * q1 * t1 * c.y;
                o.z = q2 * q2 * t2 * c.z;
                o.w = q3 * q3 * t3 * c.w;
                __stcs(reinterpret_cast<float4*>(out + v), o);
            } else if (v < n) {
                for (int k = v; k < n; k++) {
                    float l = (k >= 3)    ? __ldg(f + k - 3) : 0.0f;
                    float r = (k + 2 < n) ? __ldg(f + k + 2) : 0.0f;
                    float d = (l - r) * 0.2f;
                    float ch = (k == 0) ? 0.0f : d * d * invS;
                    float t = 1.0f - ch;
                    float q = t * t;
                    out[k] = q * q * t * __ldg(f + k);
                }
            }
        }
    }
}

// --------------------------------------------------------------------------
__global__ void __launch_bounds__(TPB, 6) k_fused(const float* __restrict__ f,
                                                  float* __restrict__ out, int n) {
    const int tid  = threadIdx.x;
    const int lane = tid & 31;
    const int warp = tid >> 5;

    // contiguous near-equal unit split
    const int nunits = (n + UNIT - 1) / UNIT;
    const int per = nunits / GRID;
    const int rem = nunits % GRID;
    const int b = blockIdx.x;
    const int start_u = b * per + (b < rem ? b : rem);
    const int cnt     = per + (b < rem ? 1 : 0);
    const int ngroups = cnt / 5;
    const int tail    = cnt - ngroups * 5;
    const int tail_u  = start_u + ngroups * 5;

    __shared__ float  s_w[TPB / 32];
    __shared__ double s_d[TPB / 32];
    __shared__ float  s_invS;
    __shared__ int    s_last;

    // ======================= phase 1 =======================
    float acc = 0.0f;
    for (int g = 0; g < ngroups; g++)
        acc += p1_group<5>(f, (start_u + g * 5) * UNIT, tid, lane, n);
    switch (tail) {
        case 4: acc += p1_group<4>(f, tail_u * UNIT, tid, lane, n); break;
        case 3: acc += p1_group<3>(f, tail_u * UNIT, tid, lane, n); break;
        case 2: acc += p1_group<2>(f, tail_u * UNIT, tid, lane, n); break;
        case 1: acc += p1_group<1>(f, tail_u * UNIT, tid, lane, n); break;
        default: break;
    }

    #pragma unroll
    for (int o = 16; o > 0; o >>= 1)
        acc += __shfl_down_sync(FULL, acc, o);
    if (lane == 0) s_w[warp] = acc;
    __syncthreads();

    // ======================= grid sync =======================
    if (tid == 0) {
        float bsum = 0.0f;
        #pragma unroll
        for (int w = 0; w < TPB / 32; w++) bsum += s_w[w];
        g_part[blockIdx.x] = bsum;
        __threadfence();
        unsigned long long ticket = atomicAdd(&g_arrive, 1ULL);
        unsigned long long gen = ticket / (unsigned long long)GRID;
        int last = ((int)(ticket % (unsigned long long)GRID) == GRID - 1);
        s_last = last;
        if (!last) {
            while (*((volatile unsigned long long*)&g_release) < gen + 1ULL) {
                __nanosleep(32);
            }
            __threadfence();
            s_invS = *((volatile float*)&g_invS);
        }
    }
    __syncthreads();

    if (s_last) {
        __threadfence();
        double a = 0.0;
        for (int i = tid; i < GRID; i += TPB)
            a += (double)g_part[i];
        #pragma unroll
        for (int o = 16; o > 0; o >>= 1)
            a += __shfl_down_sync(FULL, a, o);
        if (lane == 0) s_d[warp] = a;
        __syncthreads();
        if (tid == 0) {
            double s = 0.0;
            #pragma unroll
            for (int w = 0; w < TPB / 32; w++) s += s_d[w];
            float inv = (float)(1.0 / s);
            s_invS = inv;
            *((volatile float*)&g_invS) = inv;
            __threadfence();
            atomicAdd(&g_release, 1ULL);
        }
        __syncthreads();
    }

    const float invS = s_invS;

    // ======================= phase 2 (reverse: L1-hot first) ================
    switch (tail) {
        case 4: p2_group<4>(f, out, tail_u * UNIT, tid, lane, n, invS); break;
        case 3: p2_group<3>(f, out, tail_u * UNIT, tid, lane, n, invS); break;
        case 2: p2_group<2>(f, out, tail_u * UNIT, tid, lane, n, invS); break;
        case 1: p2_group<1>(f, out, tail_u * UNIT, tid, lane, n, invS); break;
        default: break;
    }
    for (int g = ngroups - 1; g >= 0; g--)
        p2_group<5>(f, out, (start_u + g * 5) * UNIT, tid, lane, n, invS);
}

// ---------------------------------------------------------------- launch
extern "C" void kernel_launch(void* const* d_in, const int* in_sizes, int n_in,
                              void* d_out, int out_size) {
    const float* f = (const float*)d_in[0];
    float* out = (float*)d_out;
    int n = in_sizes[0];

    k_fused<<<GRID, TPB>>>(f, out, n);
}

// round 11
// speedup vs baseline: 1.0063x; 1.0063x over previous
#include <cuda_runtime.h>

// diff[k] = (f[k-3] - f[k+2]) / 5 with zero-padding outside [0,n)
// change[k] = diff[k]^2 for k>=1, change[0] = 0
// out[k] = (1 - change[k]/S)^5 * f[k],  S = sum(change)
//
// Single persistent kernel, block-strided groups-of-5 units (R9 frontier
// pattern) + perfectly balanced unit-granular tail. Grid sync via monotonic
// generation counters (graph-replay safe). GRID = 6 x #SMs (<= MAXGRID),
// __launch_bounds__(256,6) guarantees full residency => no spin deadlock.

#define TPB 256
#define UNIT (TPB * 4)                 // 1024 elems per unit
#define MAXGRID 1024
#define FULL 0xffffffffu

__device__ float g_part[MAXGRID];
__device__ float g_invS;
__device__ unsigned long long g_arrive  = 0;
__device__ unsigned long long g_release = 0;

// ---------------- boundary-checked single unit (slow path) -----------------
__device__ __forceinline__ float p1_unit_bound(const float* __restrict__ f,
                                               int base, int tid, int n) {
    float acc = 0.0f;
    const int v = base + tid * 4;
    if (v + 3 < n) {
        float4 c = __ldg(reinterpret_cast<const float4*>(f + v));
        float m3 = (v >= 3)    ? __ldg(f + v - 3) : 0.0f;
        float m2 = (v >= 2)    ? __ldg(f + v - 2) : 0.0f;
        float m1 = (v >= 1)    ? __ldg(f + v - 1) : 0.0f;
        float p4 = (v + 4 < n) ? __ldg(f + v + 4) : 0.0f;
        float p5 = (v + 5 < n) ? __ldg(f + v + 5) : 0.0f;
        float d0 = (m3  - c.z) * 0.2f;
        float d1 = (m2  - c.w) * 0.2f;
        float d2 = (m1  - p4 ) * 0.2f;
        float d3 = (c.x - p5 ) * 0.2f;
        float c0 = (v == 0) ? 0.0f : d0 * d0;
        acc = c0 + d1 * d1 + d2 * d2 + d3 * d3;
    } else if (v < n) {
        for (int k = v; k < n; k++) {
            float l = (k >= 3)    ? __ldg(f + k - 3) : 0.0f;
            float r = (k + 2 < n) ? __ldg(f + k + 2) : 0.0f;
            float d = (l - r) * 0.2f;
            if (k != 0) acc += d * d;
        }
    }
    return acc;
}

__device__ __forceinline__ void p2_unit_bound(const float* __restrict__ f,
                                              float* __restrict__ out,
                                              int base, int tid, int n, float invS) {
    const int v = base + tid * 4;
    if (v + 3 < n) {
        float4 c = __ldg(reinterpret_cast<const float4*>(f + v));
        float m3 = (v >= 3)    ? __ldg(f + v - 3) : 0.0f;
        float m2 = (v >= 2)    ? __ldg(f + v - 2) : 0.0f;
        float m1 = (v >= 1)    ? __ldg(f + v - 1) : 0.0f;
        float p4 = (v + 4 < n) ? __ldg(f + v + 4) : 0.0f;
        float p5 = (v + 5 < n) ? __ldg(f + v + 5) : 0.0f;
        float d0 = (m3  - c.z) * 0.2f;
        float d1 = (m2  - c.w) * 0.2f;
        float d2 = (m1  - p4 ) * 0.2f;
        float d3 = (c.x - p5 ) * 0.2f;
        float c0 = (v == 0) ? 0.0f : d0 * d0 * invS;
        float t0 = 1.0f - c0;
        float t1 = 1.0f - d1 * d1 * invS;
        float t2 = 1.0f - d2 * d2 * invS;
        float t3 = 1.0f - d3 * d3 * invS;
        float q0 = t0 * t0, q1 = t1 * t1, q2 = t2 * t2, q3 = t3 * t3;
        float4 o;
        o.x = q0 * q0 * t0 * c.x;
        o.y = q1 * q1 * t1 * c.y;
        o.z = q2 * q2 * t2 * c.z;
        o.w = q3 * q3 * t3 * c.w;
        __stcs(reinterpret_cast<float4*>(out + v), o);
    } else if (v < n) {
        for (int k = v; k < n; k++) {
            float l = (k >= 3)    ? __ldg(f + k - 3) : 0.0f;
            float r = (k + 2 < n) ? __ldg(f + k + 2) : 0.0f;
            float d = (l - r) * 0.2f;
            float ch = (k == 0) ? 0.0f : d * d * invS;
            float t = 1.0f - ch;
            float q = t * t;
            out[k] = q * q * t * __ldg(f + k);
        }
    }
}

// ---------------- generic K-unit group with arbitrary unit stride ----------
template<int K>
__device__ __forceinline__ float p1_group(const float* __restrict__ f,
                                          int base, int stride,
                                          int tid, int lane, int n) {
    float acc = 0.0f;
    if (base > 0 && base + (K - 1) * stride + UNIT + 5 <= n) {
        float4 c[K];
        #pragma unroll
        for (int j = 0; j < K; j++)
            c[j] = __ldg(reinterpret_cast<const float4*>(f + base + j * stride + tid * 4));
        #pragma unroll
        for (int j = 0; j < K; j++) {
            const int v = base + j * stride + tid * 4;
            float m3 = __shfl_up_sync(FULL, c[j].y, 1);
            float m2 = __shfl_up_sync(FULL, c[j].z, 1);
            float m1 = __shfl_up_sync(FULL, c[j].w, 1);
            float p4 = __shfl_down_sync(FULL, c[j].x, 1);
            float p5 = __shfl_down_sync(FULL, c[j].y, 1);
            if (lane == 0) {
                m3 = __ldg(f + v - 3);
                m2 = __ldg(f + v - 2);
                m1 = __ldg(f + v - 1);
            }
            if (lane == 31) {
                p4 = __ldg(f + v + 4);
                p5 = __ldg(f + v + 5);
            }
            float d0 = (m3     - c[j].z) * 0.2f;
            float d1 = (m2     - c[j].w) * 0.2f;
            float d2 = (m1     - p4    ) * 0.2f;
            float d3 = (c[j].x - p5    ) * 0.2f;
            acc += d0 * d0 + d1 * d1 + d2 * d2 + d3 * d3;
        }
    } else {
        #pragma unroll
        for (int j = 0; j < K; j++)
            acc += p1_unit_bound(f, base + j * stride, tid, n);
    }
    return acc;
}

template<int K>
__device__ __forceinline__ void p2_group(const float* __restrict__ f,
                                         float* __restrict__ out,
                                         int base, int stride,
                                         int tid, int lane, int n, float invS) {
    if (base > 0 && base + (K - 1) * stride + UNIT + 5 <= n) {
        float4 c[K];
        #pragma unroll
        for (int j = 0; j < K; j++)
            c[j] = __ldg(reinterpret_cast<const float4*>(f + base + j * stride + tid * 4));
        #pragma unroll
        for (int j = 0; j < K; j++) {
            const int v = base + j * stride + tid * 4;
            float m3 = __shfl_up_sync(FULL, c[j].y, 1);
            float m2 = __shfl_up_sync(FULL, c[j].z, 1);
            float m1 = __shfl_up_sync(FULL, c[j].w, 1);
            float p4 = __shfl_down_sync(FULL, c[j].x, 1);
            float p5 = __shfl_down_sync(FULL, c[j].y, 1);
            if (lane == 0) {
                m3 = __ldg(f + v - 3);
                m2 = __ldg(f + v - 2);
                m1 = __ldg(f + v - 1);
            }
            if (lane == 31) {
                p4 = __ldg(f + v + 4);
                p5 = __ldg(f + v + 5);
            }
            float d0 = (m3     - c[j].z) * 0.2f;
            float d1 = (m2     - c[j].w) * 0.2f;
            float d2 = (m1     - p4    ) * 0.2f;
            float d3 = (c[j].x - p5    ) * 0.2f;
            float t0 = 1.0f - d0 * d0 * invS;
            float t1 = 1.0f - d1 * d1 * invS;
            float t2 = 1.0f - d2 * d2 * invS;
            float t3 = 1.0f - d3 * d3 * invS;
            float q0 = t0 * t0, q1 = t1 * t1, q2 = t2 * t2, q3 = t3 * t3;
            float4 o;
            o.x = q0 * q0 * t0 * c[j].x;
            o.y = q1 * q1 * t1 * c[j].y;
            o.z = q2 * q2 * t2 * c[j].z;
            o.w = q3 * q3 * t3 * c[j].w;
            __stcs(reinterpret_cast<float4*>(out + v), o);
        }
    } else {
        #pragma unroll
        for (int j = 0; j < K; j++)
            p2_unit_bound(f, out, base + j * stride, tid, n, invS);
    }
}

// --------------------------------------------------------------------------
__global__ void __launch_bounds__(TPB, 6) k_fused(const float* __restrict__ f,
                                                  float* __restrict__ out, int n) {
    const int tid  = threadIdx.x;
    const int lane = tid & 31;
    const int warp = tid >> 5;
    const int grid = gridDim.x;
    const int bid  = blockIdx.x;

    // schedule: balanced block-strided groups of 5 units + unit-granular tail
    const int nunits = (n + UNIT - 1) / UNIT;
    const int gtot   = nunits / 5;
    const int gbal   = (gtot / grid) * grid;    // perfectly balanced groups
    const int ubal   = gbal * 5;                // first tail unit
    const int tailN  = nunits - ubal;
    const int m      = (bid < tailN) ? ((tailN - bid + grid - 1) / grid) : 0;
    const int ustr   = grid * UNIT;             // tail unit stride (elems)

    __shared__ float  s_w[TPB / 32];
    __shared__ double s_d[TPB / 32];
    __shared__ float  s_invS;
    __shared__ int    s_last;

    // ======================= phase 1 =======================
    float acc = 0.0f;
    for (int g = bid; g < gbal; g += grid)
        acc += p1_group<5>(f, g * (5 * UNIT), UNIT, tid, lane, n);
    {
        int j = 0;
        while (m - j >= 4) {
            acc += p1_group<4>(f, (ubal + bid + j * grid) * UNIT, ustr, tid, lane, n);
            j += 4;
        }
        switch (m - j) {
            case 3: acc += p1_group<3>(f, (ubal + bid + j * grid) * UNIT, ustr, tid, lane, n); break;
            case 2: acc += p1_group<2>(f, (ubal + bid + j * grid) * UNIT, ustr, tid, lane, n); break;
            case 1: acc += p1_group<1>(f, (ubal + bid + j * grid) * UNIT, ustr, tid, lane, n); break;
            default: break;
        }
    }

    #pragma unroll
    for (int o = 16; o > 0; o >>= 1)
        acc += __shfl_down_sync(FULL, acc, o);
    if (lane == 0) s_w[warp] = acc;
    __syncthreads();

    // ======================= grid sync =======================
    if (tid == 0) {
        float bsum = 0.0f;
        #pragma unroll
        for (int w = 0; w < TPB / 32; w++) bsum += s_w[w];
        g_part[bid] = bsum;
        __threadfence();
        unsigned long long ticket = atomicAdd(&g_arrive, 1ULL);
        unsigned long long gen = ticket / (unsigned long long)grid;
        int last = ((int)(ticket % (unsigned long long)grid) == grid - 1);
        s_last = last;
        if (!last) {
            while (*((volatile unsigned long long*)&g_release) < gen + 1ULL) {
                __nanosleep(32);
            }
            __threadfence();
            s_invS = *((volatile float*)&g_invS);
        }
    }
    __syncthreads();

    if (s_last) {
        __threadfence();
        double a = 0.0;
        for (int i = tid; i < grid; i += TPB)
            a += (double)g_part[i];
        #pragma unroll
        for (int o = 16; o > 0; o >>= 1)
            a += __shfl_down_sync(FULL, a, o);
        if (lane == 0) s_d[warp] = a;
        __syncthreads();
        if (tid == 0) {
            double s = 0.0;
            #pragma unroll
            for (int w = 0; w < TPB / 32; w++) s += s_d[w];
            float inv = (float)(1.0 / s);
            s_invS = inv;
            *((volatile float*)&g_invS) = inv;
            __threadfence();
            atomicAdd(&g_release, 1ULL);
        }
        __syncthreads();
    }

    const float invS = s_invS;

    // ======================= phase 2 (same schedule, warm L2) ===============
    for (int g = bid; g < gbal; g += grid)
        p2_group<5>(f, out, g * (5 * UNIT), UNIT, tid, lane, n, invS);
    {
        int j = 0;
        while (m - j >= 4) {
            p2_group<4>(f, out, (ubal + bid + j * grid) * UNIT, ustr, tid, lane, n, invS);
            j += 4;
        }
        switch (m - j) {
            case 3: p2_group<3>(f, out, (ubal + bid + j * grid) * UNIT, ustr, tid, lane, n, invS); break;
            case 2: p2_group<2>(f, out, (ubal + bid + j * grid) * UNIT, ustr, tid, lane, n, invS); break;
            case 1: p2_group<1>(f, out, (ubal + bid + j * grid) * UNIT, ustr, tid, lane, n, invS); break;
            default: break;
        }
    }
}

// ---------------------------------------------------------------- launch
extern "C" void kernel_launch(void* const* d_in, const int* in_sizes, int n_in,
                              void* d_out, int out_size) {
    const float* f = (const float*)d_in[0];
    float* out = (float*)d_out;
    int n = in_sizes[0];

    int sm = 0;
    if (cudaDeviceGetAttribute(&sm, cudaDevAttrMultiProcessorCount, 0) != cudaSuccess || sm <= 0)
        sm = 148;
    int grid = sm * 6;                 // fully resident (launch_bounds(256,6))
    if (grid > MAXGRID) grid = MAXGRID;

    k_fused<<<grid, TPB>>>(f, out, n);
}

// round 12
// speedup vs baseline: 1.0693x; 1.0626x over previous
#include <cuda_runtime.h>

// diff[k] = (f[k-3] - f[k+2]) / 5 with zero-padding outside [0,n)
// change[k] = diff[k]^2 for k>=1, change[0] = 0
// out[k] = (1 - change[k]/S)^5 * f[k],  S = sum(change)
//
// Single persistent kernel (R9 structure: block-strided 5120-elem super-
// chunks, batched MLP-5 loads + shuffle halo). Grid sync via monotonic
// generation counters (graph-replay safe). NEW: while waiting at the sync,
// each block prefetches its first phase-2 super-chunk (+halo) into shared
// memory, hiding the sync bubble; phase2 consumes chunk 0 from smem.

#define TPB 256
#define VPT 5                              // float4 vectors per thread
#define EPB (TPB * VPT * 4)                // 5120 elems per super-chunk
#define GRID 888                           // 148 SMs x 6 blocks, fully resident
#define TILE_F (EPB + 16)                  // [-4, +12) halo => 5136 floats
#define FULL 0xffffffffu

__device__ float g_part[GRID];
__device__ float g_invS;
__device__ unsigned long long g_arrive  = 0;   // monotonic across graph replays
__device__ unsigned long long g_release = 0;

__global__ void __launch_bounds__(TPB, 6) k_fused(const float* __restrict__ f,
                                                  float* __restrict__ out, int n) {
    const int tid  = threadIdx.x;
    const int lane = tid & 31;
    const int warp = tid >> 5;
    const int nchunks = (n + EPB - 1) / EPB;

    __shared__ alignas(16) float s_tile[TILE_F];
    __shared__ float  s_w[TPB / 32];
    __shared__ double s_d[TPB / 32];
    __shared__ float  s_invS;
    __shared__ int    s_last;

    // ======================= phase 1: sum of change =======================
    float acc = 0.0f;
    for (int sc = blockIdx.x; sc < nchunks; sc += GRID) {
        const int base = sc * EPB;
        if (sc > 0 && base + EPB + 5 <= n) {
            float4 c[VPT];
            #pragma unroll
            for (int j = 0; j < VPT; j++) {
                const int v = base + j * (TPB * 4) + tid * 4;
                c[j] = __ldg(reinterpret_cast<const float4*>(f + v));
            }
            #pragma unroll
            for (int j = 0; j < VPT; j++) {
                const int v = base + j * (TPB * 4) + tid * 4;
                float m3 = __shfl_up_sync(FULL, c[j].y, 1);
                float m2 = __shfl_up_sync(FULL, c[j].z, 1);
                float m1 = __shfl_up_sync(FULL, c[j].w, 1);
                float p4 = __shfl_down_sync(FULL, c[j].x, 1);
                float p5 = __shfl_down_sync(FULL, c[j].y, 1);
                if (lane == 0) {
                    m3 = __ldg(f + v - 3);
                    m2 = __ldg(f + v - 2);
                    m1 = __ldg(f + v - 1);
                }
                if (lane == 31) {
                    p4 = __ldg(f + v + 4);
                    p5 = __ldg(f + v + 5);
                }
                float d0 = (m3     - c[j].z) * 0.2f;
                float d1 = (m2     - c[j].w) * 0.2f;
                float d2 = (m1     - p4    ) * 0.2f;
                float d3 = (c[j].x - p5    ) * 0.2f;
                acc += d0 * d0 + d1 * d1 + d2 * d2 + d3 * d3;
            }
        } else {
            #pragma unroll
            for (int j = 0; j < VPT; j++) {
                const int v = base + j * (TPB * 4) + tid * 4;
                if (v + 3 < n) {
                    float4 c = __ldg(reinterpret_cast<const float4*>(f + v));
                    float m3 = (v >= 3)     ? __ldg(f + v - 3) : 0.0f;
                    float m2 = (v >= 2)     ? __ldg(f + v - 2) : 0.0f;
                    float m1 = (v >= 1)     ? __ldg(f + v - 1) : 0.0f;
                    float p4 = (v + 4 < n)  ? __ldg(f + v + 4) : 0.0f;
                    float p5 = (v + 5 < n)  ? __ldg(f + v + 5) : 0.0f;
                    float d0 = (m3  - c.z) * 0.2f;
                    float d1 = (m2  - c.w) * 0.2f;
                    float d2 = (m1  - p4 ) * 0.2f;
                    float d3 = (c.x - p5 ) * 0.2f;
                    float c0 = (v == 0) ? 0.0f : d0 * d0;
                    acc += c0 + d1 * d1 + d2 * d2 + d3 * d3;
                } else if (v < n) {
                    for (int k = v; k < n; k++) {
                        float l = (k >= 3)    ? __ldg(f + k - 3) : 0.0f;
                        float r = (k + 2 < n) ? __ldg(f + k + 2) : 0.0f;
                        float d = (l - r) * 0.2f;
                        if (k != 0) acc += d * d;
                    }
                }
            }
        }
    }

    #pragma unroll
    for (int o = 16; o > 0; o >>= 1)
        acc += __shfl_down_sync(FULL, acc, o);
    if (lane == 0) s_w[warp] = acc;
    __syncthreads();

    // ======================= arrive =======================
    if (tid == 0) {
        float b = 0.0f;
        #pragma unroll
        for (int w = 0; w < TPB / 32; w++) b += s_w[w];
        g_part[blockIdx.x] = b;
        __threadfence();
        unsigned long long ticket = atomicAdd(&g_arrive, 1ULL);
        s_last = ((int)(ticket % (unsigned long long)GRID) == GRID - 1);
    }
    __syncthreads();

    // first phase-2 super-chunk of this block (prefetch target)
    const int sc0   = blockIdx.x;
    const int base0 = sc0 * EPB;
    const bool pref = (sc0 > 0) && (sc0 < nchunks) && (base0 + EPB + 12 <= n);

    if (s_last) {
        // -------- last block: reduce + release FIRST, then prefetch --------
        __threadfence();
        double a = 0.0;
        for (int i = tid; i < GRID; i += TPB)
            a += (double)g_part[i];
        #pragma unroll
        for (int o = 16; o > 0; o >>= 1)
            a += __shfl_down_sync(FULL, a, o);
        if (lane == 0) s_d[warp] = a;
        __syncthreads();
        if (tid == 0) {
            double s = 0.0;
            #pragma unroll
            for (int w = 0; w < TPB / 32; w++) s += s_d[w];
            float inv = (float)(1.0 / s);
            s_invS = inv;
            *((volatile float*)&g_invS) = inv;
            __threadfence();
            atomicAdd(&g_release, 1ULL);
        }
        if (pref) {
            const float4* src = reinterpret_cast<const float4*>(f + base0 - 4);
            float4* dst = reinterpret_cast<float4*>(s_tile);
            for (int i = tid; i < TILE_F / 4; i += TPB)
                dst[i] = __ldg(src + i);
        }
    } else {
        // -------- other blocks: prefetch chunk 0 into smem, tid0 spins -----
        if (pref) {
            const float4* src = reinterpret_cast<const float4*>(f + base0 - 4);
            float4* dst = reinterpret_cast<float4*>(s_tile);
            for (int i = tid; i < TILE_F / 4; i += TPB)
                dst[i] = __ldg(src + i);
        }
        if (tid == 0) {
            while (*((volatile unsigned long long*)&g_release) == 0ULL ||
                   *((volatile float*)&g_invS) == 0.0f) {
                // generation check: release counter advances once per launch.
                // Use >= gen+1 form with the ticket's generation.
                break;   // placeholder, replaced below
            }
        }
    }

    // Proper generation-based wait (all blocks, tid0 only).
    // (The break above never executes a wait; do the real wait here so both
    //  branches share one code path.)
    if (!s_last && tid == 0) {
        // re-derive this launch's generation from our ticket-free arrival:
        // g_release is monotonically increasing, one increment per launch.
        // We must wait until it exceeds the value it had when this launch's
        // blocks began. Since g_arrive % GRID == 0 exactly at launch start,
        // generation = (observed arrivals - 1) / GRID for our ticket. We
        // avoid storing the ticket per-thread by re-reading g_arrive is racy;
        // instead rely on: release < ceil(arrive/GRID) until last block
        // releases this generation.
        // Simplest correct form: wait until g_release advances past the
        // generation of OUR arrival, which tid0 recorded implicitly via
        // s_last==0. Recompute via atomicAdd(0):
        unsigned long long seen = atomicAdd(&g_arrive, 0ULL);   // >= our ticket+1
        unsigned long long gen  = (seen - 1ULL) / (unsigned long long)GRID;
        while (*((volatile unsigned long long*)&g_release) < gen + 1ULL) {
            __nanosleep(32);
        }
        __threadfence();
        s_invS = *((volatile float*)&g_invS);
    }
    __syncthreads();

    const float invS = s_invS;

    // ======================= phase 2 =======================
    // chunk 0 from smem (prefetched), rest from (L2-warm) global
    if (sc0 < nchunks) {
        if (pref) {
            #pragma unroll
            for (int j = 0; j < VPT; j++) {
                const int idx = 4 + j * (TPB * 4) + tid * 4;    // 16B-aligned
                float4 c = *reinterpret_cast<const float4*>(s_tile + idx);
                float m3 = s_tile[idx - 3];
                float m2 = s_tile[idx - 2];
                float m1 = s_tile[idx - 1];
                float p4 = s_tile[idx + 4];
                float p5 = s_tile[idx + 5];
                float d0 = (m3  - c.z) * 0.2f;
                float d1 = (m2  - c.w) * 0.2f;
                float d2 = (m1  - p4 ) * 0.2f;
                float d3 = (c.x - p5 ) * 0.2f;
                float t0 = 1.0f - d0 * d0 * invS;
                float t1 = 1.0f - d1 * d1 * invS;
                float t2 = 1.0f - d2 * d2 * invS;
                float t3 = 1.0f - d3 * d3 * invS;
                float q0 = t0 * t0, q1 = t1 * t1, q2 = t2 * t2, q3 = t3 * t3;
                float4 o;
                o.x = q0 * q0 * t0 * c.x;
                o.y = q1 * q1 * t1 * c.y;
                o.z = q2 * q2 * t2 * c.z;
                o.w = q3 * q3 * t3 * c.w;
                __stcs(reinterpret_cast<float4*>(out + base0 + j * (TPB * 4) + tid * 4), o);
            }
        } else {
            #pragma unroll
            for (int j = 0; j < VPT; j++) {
                const int v = base0 + j * (TPB * 4) + tid * 4;
                if (v + 3 < n) {
                    float4 c = __ldg(reinterpret_cast<const float4*>(f + v));
                    float m3 = (v >= 3)    ? __ldg(f + v - 3) : 0.0f;
                    float m2 = (v >= 2)    ? __ldg(f + v - 2) : 0.0f;
                    float m1 = (v >= 1)    ? __ldg(f + v - 1) : 0.0f;
                    float p4 = (v + 4 < n) ? __ldg(f + v + 4) : 0.0f;
                    float p5 = (v + 5 < n) ? __ldg(f + v + 5) : 0.0f;
                    float d0 = (m3  - c.z) * 0.2f;
                    float d1 = (m2  - c.w) * 0.2f;
                    float d2 = (m1  - p4 ) * 0.2f;
                    float d3 = (c.x - p5 ) * 0.2f;
                    float c0 = (v == 0) ? 0.0f : d0 * d0 * invS;
                    float t0 = 1.0f - c0;
                    float t1 = 1.0f - d1 * d1 * invS;
                    float t2 = 1.0f - d2 * d2 * invS;
                    float t3 = 1.0f - d3 * d3 * invS;
                    float q0 = t0 * t0, q1 = t1 * t1, q2 = t2 * t2, q3 = t3 * t3;
                    float4 o;
                    o.x = q0 * q0 * t0 * c.x;
                    o.y = q1 * q1 * t1 * c.y;
                    o.z = q2 * q2 * t2 * c.z;
                    o.w = q3 * q3 * t3 * c.w;
                    __stcs(reinterpret_cast<float4*>(out + v), o);
                } else if (v < n) {
                    for (int k = v; k < n; k++) {
                        float l = (k >= 3)    ? __ldg(f + k - 3) : 0.0f;
                        float r = (k + 2 < n) ? __ldg(f + k + 2) : 0.0f;
                        float d = (l - r) * 0.2f;
                        float ch = (k == 0) ? 0.0f : d * d * invS;
                        float t = 1.0f - ch;
                        float q = t * t;
                        out[k] = q * q * t * __ldg(f + k);
                    }
                }
            }
        }
    }

    for (int sc = sc0 + GRID; sc < nchunks; sc += GRID) {
        const int base = sc * EPB;
        if (base + EPB + 5 <= n) {
            float4 c[VPT];
            #pragma unroll
            for (int j = 0; j < VPT; j++) {
                const int v = base + j * (TPB * 4) + tid * 4;
                c[j] = __ldg(reinterpret_cast<const float4*>(f + v));
            }
            #pragma unroll
            for (int j = 0; j < VPT; j++) {
                const int v = base + j * (TPB * 4) + tid * 4;
                float m3 = __shfl_up_sync(FULL, c[j].y, 1);
                float m2 = __shfl_up_sync(FULL, c[j].z, 1);
                float m1 = __shfl_up_sync(FULL, c[j].w, 1);
                float p4 = __shfl_down_sync(FULL, c[j].x, 1);
                float p5 = __shfl_down_sync(FULL, c[j].y, 1);
                if (lane == 0) {
                    m3 = __ldg(f + v - 3);
                    m2 = __ldg(f + v - 2);
                    m1 = __ldg(f + v - 1);
                }
                if (lane == 31) {
                    p4 = __ldg(f + v + 4);
                    p5 = __ldg(f + v + 5);
                }
                float d0 = (m3     - c[j].z) * 0.2f;
                float d1 = (m2     - c[j].w) * 0.2f;
                float d2 = (m1     - p4    ) * 0.2f;
                float d3 = (c[j].x - p5    ) * 0.2f;
                float t0 = 1.0f - d0 * d0 * invS;
                float t1 = 1.0f - d1 * d1 * invS;
                float t2 = 1.0f - d2 * d2 * invS;
                float t3 = 1.0f - d3 * d3 * invS;
                float q0 = t0 * t0, q1 = t1 * t1, q2 = t2 * t2, q3 = t3 * t3;
                float4 o;
                o.x = q0 * q0 * t0 * c[j].x;
                o.y = q1 * q1 * t1 * c[j].y;
                o.z = q2 * q2 * t2 * c[j].z;
                o.w = q3 * q3 * t3 * c[j].w;
                __stcs(reinterpret_cast<float4*>(out + v), o);
            }
        } else {
            #pragma unroll
            for (int j = 0; j < VPT; j++) {
                const int v = base + j * (TPB * 4) + tid * 4;
                if (v + 3 < n) {
                    float4 c = __ldg(reinterpret_cast<const float4*>(f + v));
                    float m3 = (v >= 3)    ? __ldg(f + v - 3) : 0.0f;
                    float m2 = (v >= 2)    ? __ldg(f + v - 2) : 0.0f;
                    float m1 = (v >= 1)    ? __ldg(f + v - 1) : 0.0f;
                    float p4 = (v + 4 < n) ? __ldg(f + v + 4) : 0.0f;
                    float p5 = (v + 5 < n) ? __ldg(f + v + 5) : 0.0f;
                    float d0 = (m3  - c.z) * 0.2f;
                    float d1 = (m2  - c.w) * 0.2f;
                    float d2 = (m1  - p4 ) * 0.2f;
                    float d3 = (c.x - p5 ) * 0.2f;
                    float c0 = (v == 0) ? 0.0f : d0 * d0 * invS;
                    float t0 = 1.0f - c0;
                    float t1 = 1.0f - d1 * d1 * invS;
                    float t2 = 1.0f - d2 * d2 * invS;
                    float t3 = 1.0f - d3 * d3 * invS;
                    float q0 = t0 * t0, q1 = t1 * t1, q2 = t2 * t2, q3 = t3 * t3;
                    float4 o;
                    o.x = q0 * q0 * t0 * c.x;
                    o.y = q1 * q1 * t1 * c.y;
                    o.z = q2 * q2 * t2 * c.z;
                    o.w = q3 * q3 * t3 * c.w;
                    __stcs(reinterpret_cast<float4*>(out + v), o);
                } else if (v < n) {
                    for (int k = v; k < n; k++) {
                        float l = (k >= 3)    ? __ldg(f + k - 3) : 0.0f;
                        float r = (k + 2 < n) ? __ldg(f + k + 2) : 0.0f;
                        float d = (l - r) * 0.2f;
                        float ch = (k == 0) ? 0.0f : d * d * invS;
                        float t = 1.0f - ch;
                        float q = t * t;
                        out[k] = q * q * t * __ldg(f + k);
                    }
                }
            }
        }
    }
}

// ---------------------------------------------------------------- launch
extern "C" void kernel_launch(void* const* d_in, const int* in_sizes, int n_in,
                              void* d_out, int out_size) {
    const float* f = (const float*)d_in[0];
    float* out = (float*)d_out;
    int n = in_sizes[0];

    k_fused<<<GRID, TPB>>>(f, out, n);
}

// round 13
// speedup vs baseline: 1.0786x; 1.0087x over previous
#include <cuda_runtime.h>

// diff[k] = (f[k-3] - f[k+2]) / 5 with zero-padding outside [0,n)
// change[k] = diff[k]^2 for k>=1, change[0] = 0
// out[k] = (1 - change[k]/S)^5 * f[k],  S = sum(change)
//
// Single persistent kernel, block-stride super-chunks (R9 schedule):
//   phase1 (partial sums, batched MLP-5 loads + shuffle halo)
//   -> generation-counter grid sync (graph-replay safe)
//   -> phase2 over the SAME chunks in REVERSE order (last-read chunk first:
//      its lines are hottest in L1/L2, converting early phase-2 reads into
//      L1 hits and cutting LTS traffic), streaming (evict-first) stores.

#define TPB 256
#define VPT 5                              // float4 vectors per thread (batched)
#define EPB (TPB * VPT * 4)                // 5120 elems per super-chunk
#define GRID 888                           // 148 SMs x 6 blocks, fully resident
#define FULL 0xffffffffu

__device__ float g_part[GRID];
__device__ float g_invS;
__device__ unsigned long long g_arrive  = 0;   // monotonic across graph replays
__device__ unsigned long long g_release = 0;

__global__ void __launch_bounds__(TPB, 6) k_fused(const float* __restrict__ f,
                                                  float* __restrict__ out, int n) {
    const int tid  = threadIdx.x;
    const int lane = tid & 31;
    const int warp = tid >> 5;
    const int nchunks = (n + EPB - 1) / EPB;

    __shared__ float  s_w[TPB / 32];
    __shared__ double s_d[TPB / 32];
    __shared__ float  s_invS;
    __shared__ int    s_last;

    // ======================= phase 1: sum of change =======================
    float acc = 0.0f;
    for (int sc = blockIdx.x; sc < nchunks; sc += GRID) {
        const int base = sc * EPB;
        if (sc > 0 && base + EPB + 5 <= n) {
            // interior: batch 5 main loads (deep MLP), halo via shuffle
            float4 c[VPT];
            #pragma unroll
            for (int j = 0; j < VPT; j++) {
                const int v = base + j * (TPB * 4) + tid * 4;
                c[j] = __ldg(reinterpret_cast<const float4*>(f + v));
            }
            #pragma unroll
            for (int j = 0; j < VPT; j++) {
                const int v = base + j * (TPB * 4) + tid * 4;
                float m3 = __shfl_up_sync(FULL, c[j].y, 1);
                float m2 = __shfl_up_sync(FULL, c[j].z, 1);
                float m1 = __shfl_up_sync(FULL, c[j].w, 1);
                float p4 = __shfl_down_sync(FULL, c[j].x, 1);
                float p5 = __shfl_down_sync(FULL, c[j].y, 1);
                if (lane == 0) {
                    m3 = __ldg(f + v - 3);
                    m2 = __ldg(f + v - 2);
                    m1 = __ldg(f + v - 1);
                }
                if (lane == 31) {
                    p4 = __ldg(f + v + 4);
                    p5 = __ldg(f + v + 5);
                }
                float d0 = (m3     - c[j].z) * 0.2f;
                float d1 = (m2     - c[j].w) * 0.2f;
                float d2 = (m1     - p4    ) * 0.2f;
                float d3 = (c[j].x - p5    ) * 0.2f;
                acc += d0 * d0 + d1 * d1 + d2 * d2 + d3 * d3;
            }
        } else {
            #pragma unroll
            for (int j = 0; j < VPT; j++) {
                const int v = base + j * (TPB * 4) + tid * 4;
                if (v + 3 < n) {
                    float4 c = __ldg(reinterpret_cast<const float4*>(f + v));
                    float m3 = (v >= 3)     ? __ldg(f + v - 3) : 0.0f;
                    float m2 = (v >= 2)     ? __ldg(f + v - 2) : 0.0f;
                    float m1 = (v >= 1)     ? __ldg(f + v - 1) : 0.0f;
                    float p4 = (v + 4 < n)  ? __ldg(f + v + 4) : 0.0f;
                    float p5 = (v + 5 < n)  ? __ldg(f + v + 5) : 0.0f;
                    float d0 = (m3  - c.z) * 0.2f;
                    float d1 = (m2  - c.w) * 0.2f;
                    float d2 = (m1  - p4 ) * 0.2f;
                    float d3 = (c.x - p5 ) * 0.2f;
                    float c0 = (v == 0) ? 0.0f : d0 * d0;
                    acc += c0 + d1 * d1 + d2 * d2 + d3 * d3;
                } else if (v < n) {
                    for (int k = v; k < n; k++) {
                        float l = (k >= 3)    ? __ldg(f + k - 3) : 0.0f;
                        float r = (k + 2 < n) ? __ldg(f + k + 2) : 0.0f;
                        float d = (l - r) * 0.2f;
                        if (k != 0) acc += d * d;
                    }
                }
            }
        }
    }

    #pragma unroll
    for (int o = 16; o > 0; o >>= 1)
        acc += __shfl_down_sync(FULL, acc, o);
    if (lane == 0) s_w[warp] = acc;
    __syncthreads();

    // ======================= grid sync (generation counters) ==============
    if (tid == 0) {
        float b = 0.0f;
        #pragma unroll
        for (int w = 0; w < TPB / 32; w++) b += s_w[w];
        g_part[blockIdx.x] = b;
        __threadfence();
        unsigned long long ticket = atomicAdd(&g_arrive, 1ULL);
        unsigned long long gen = ticket / (unsigned long long)GRID;
        int last = ((int)(ticket % (unsigned long long)GRID) == GRID - 1);
        s_last = last;
        if (!last) {
            while (*((volatile unsigned long long*)&g_release) < gen + 1ULL) {
                __nanosleep(32);
            }
            __threadfence();
            s_invS = *((volatile float*)&g_invS);
        }
    }
    __syncthreads();

    if (s_last) {   // block-uniform
        __threadfence();
        double a = 0.0;
        for (int i = tid; i < GRID; i += TPB)
            a += (double)g_part[i];
        #pragma unroll
        for (int o = 16; o > 0; o >>= 1)
            a += __shfl_down_sync(FULL, a, o);
        if (lane == 0) s_d[warp] = a;
        __syncthreads();
        if (tid == 0) {
            double s = 0.0;
            #pragma unroll
            for (int w = 0; w < TPB / 32; w++) s += s_d[w];
            float inv = (float)(1.0 / s);
            s_invS = inv;
            *((volatile float*)&g_invS) = inv;
            __threadfence();
            atomicAdd(&g_release, 1ULL);
        }
        __syncthreads();
    }

    const float invS = s_invS;

    // ======================= phase 2: scale + write ========================
    // Same block-stride chunks as phase 1, REVERSE order: the block's most
    // recently read chunk is processed first while its lines are L1/L2-hot.
    const int nmine = (nchunks > blockIdx.x)
                    ? ((nchunks - blockIdx.x + GRID - 1) / GRID) : 0;
    for (int i = nmine - 1; i >= 0; i--) {
        const int sc = blockIdx.x + i * GRID;
        const int base = sc * EPB;
        if (sc > 0 && base + EPB + 5 <= n) {
            float4 c[VPT];
            #pragma unroll
            for (int j = 0; j < VPT; j++) {
                const int v = base + j * (TPB * 4) + tid * 4;
                c[j] = __ldg(reinterpret_cast<const float4*>(f + v));
            }
            #pragma unroll
            for (int j = 0; j < VPT; j++) {
                const int v = base + j * (TPB * 4) + tid * 4;
                float m3 = __shfl_up_sync(FULL, c[j].y, 1);
                float m2 = __shfl_up_sync(FULL, c[j].z, 1);
                float m1 = __shfl_up_sync(FULL, c[j].w, 1);
                float p4 = __shfl_down_sync(FULL, c[j].x, 1);
                float p5 = __shfl_down_sync(FULL, c[j].y, 1);
                if (lane == 0) {
                    m3 = __ldg(f + v - 3);
                    m2 = __ldg(f + v - 2);
                    m1 = __ldg(f + v - 1);
                }
                if (lane == 31) {
                    p4 = __ldg(f + v + 4);
                    p5 = __ldg(f + v + 5);
                }
                float d0 = (m3     - c[j].z) * 0.2f;
                float d1 = (m2     - c[j].w) * 0.2f;
                float d2 = (m1     - p4    ) * 0.2f;
                float d3 = (c[j].x - p5    ) * 0.2f;
                float t0 = 1.0f - d0 * d0 * invS;
                float t1 = 1.0f - d1 * d1 * invS;
                float t2 = 1.0f - d2 * d2 * invS;
                float t3 = 1.0f - d3 * d3 * invS;
                float q0 = t0 * t0, q1 = t1 * t1, q2 = t2 * t2, q3 = t3 * t3;
                float4 o;
                o.x = q0 * q0 * t0 * c[j].x;
                o.y = q1 * q1 * t1 * c[j].y;
                o.z = q2 * q2 * t2 * c[j].z;
                o.w = q3 * q3 * t3 * c[j].w;
                __stcs(reinterpret_cast<float4*>(out + v), o);
            }
        } else {
            #pragma unroll
            for (int j = 0; j < VPT; j++) {
                const int v = base + j * (TPB * 4) + tid * 4;
                if (v + 3 < n) {
                    float4 c = __ldg(reinterpret_cast<const float4*>(f + v));
                    float m3 = (v >= 3)    ? __ldg(f + v - 3) : 0.0f;
                    float m2 = (v >= 2)    ? __ldg(f + v - 2) : 0.0f;
                    float m1 = (v >= 1)    ? __ldg(f + v - 1) : 0.0f;
                    float p4 = (v + 4 < n) ? __ldg(f + v + 4) : 0.0f;
                    float p5 = (v + 5 < n) ? __ldg(f + v + 5) : 0.0f;
                    float d0 = (m3  - c.z) * 0.2f;
                    float d1 = (m2  - c.w) * 0.2f;
                    float d2 = (m1  - p4 ) * 0.2f;
                    float d3 = (c.x - p5 ) * 0.2f;
                    float c0 = (v == 0) ? 0.0f : d0 * d0 * invS;
                    float t0 = 1.0f - c0;
                    float t1 = 1.0f - d1 * d1 * invS;
                    float t2 = 1.0f - d2 * d2 * invS;
                    float t3 = 1.0f - d3 * d3 * invS;
                    float q0 = t0 * t0, q1 = t1 * t1, q2 = t2 * t2, q3 = t3 * t3;
                    float4 o;
                    o.x = q0 * q0 * t0 * c.x;
                    o.y = q1 * q1 * t1 * c.y;
                    o.z = q2 * q2 * t2 * c.z;
                    o.w = q3 * q3 * t3 * c.w;
                    __stcs(reinterpret_cast<float4*>(out + v), o);
                } else if (v < n) {
                    for (int k = v; k < n; k++) {
                        float l = (k >= 3)    ? __ldg(f + k - 3) : 0.0f;
                        float r = (k + 2 < n) ? __ldg(f + k + 2) : 0.0f;
                        float d = (l - r) * 0.2f;
                        float ch = (k == 0) ? 0.0f : d * d * invS;
                        float t = 1.0f - ch;
                        float q = t * t;
                        out[k] = q * q * t * __ldg(f + k);
                    }
                }
            }
        }
    }
}

// ---------------------------------------------------------------- launch
extern "C" void kernel_launch(void* const* d_in, const int* in_sizes, int n_in,
                              void* d_out, int out_size) {
    const float* f = (const float*)d_in[0];
    float* out = (float*)d_out;
    int n = in_sizes[0];

    k_fused<<<GRID, TPB>>>(f, out, n);
}